// round 6
// baseline (speedup 1.0000x reference)
#include <cuda_runtime.h>
#include <cstdint>
#include <math.h>

#define N_PTS   65536
#define DIM     128
#define KCODES  1024
#define KC      16          // codes per smem tile
#define CJ      8           // codes per thread per tile (half of KC)
#define ROWS_CTA 256
#define THREADS  256
#define NCTAS   (N_PTS / ROWS_CTA)   // 256

typedef unsigned long long ull;

// ---- f32x2 packed math (sm_103a); lanes are IEEE fp32 fma.rn ----
__device__ __forceinline__ ull pack2(float a, float b) {
    ull r; asm("mov.b64 %0, {%1, %2};" : "=l"(r) : "f"(a), "f"(b)); return r;
}
__device__ __forceinline__ void unpack2(ull v, float& a, float& b) {
    asm("mov.b64 {%0, %1}, %2;" : "=f"(a), "=f"(b) : "l"(v));
}
__device__ __forceinline__ ull fma2(ull a, ull b, ull c) {
    ull d; asm("fma.rn.f32x2 %0, %1, %2, %3;" : "=l"(d) : "l"(a), "l"(b), "l"(c)); return d;
}

// ---- device scratch ----
__device__ float g_bsq[KCODES];     // fl( sum_k fl(c^2) )  (exact-then-rounded)
__device__ int   g_counts[KCODES];
__device__ int   g_idx[N_PTS];
__device__ float g_bloss[512];

// smem layout (bytes)
#define SM_XS    0                         // ull  xs[128][128]  = 131072
#define SM_CS    131072                    // ull  cs[KC][128]   = 16384
#define SM_BS    (SM_CS + 16384)           // f32  bs[KC]        = 64
#define SM_EXD0  (SM_BS + 64)              // f32  [128]
#define SM_EXD1  (SM_EXD0 + 512)
#define SM_EXI0  (SM_EXD1 + 512)           // int  [128]
#define SM_EXI1  (SM_EXI0 + 512)
#define SM_RED   (SM_EXI1 + 512)           // f32  [256]
#define SM_TOTAL (SM_RED + 1024)

// ============================================================
// 1) B_k = fl( sum fl(c^2) ) computed exactly in double, + zero counts
// ============================================================
__global__ void prep_kernel(const float* __restrict__ cb) {
    int k = blockIdx.x * blockDim.x + threadIdx.x;
    if (k < KCODES) {
        const float* c = cb + (size_t)k * DIM;
        double s = 0.0;
        #pragma unroll 8
        for (int i = 0; i < DIM; i++) {
            float q = __fmul_rn(c[i], c[i]);   // elementwise c**2 rounds to f32
            s += (double)q;
        }
        g_bsq[k] = (float)s;
        g_counts[k] = 0;
    }
}

// ============================================================
// 2) Main: bit-faithful distance + argmin, 2 rows per f32x2 lanepair
// ============================================================
__global__ __launch_bounds__(THREADS, 1)
void vq_main(const float* __restrict__ x, const float* __restrict__ cb,
             float* __restrict__ outq) {
    extern __shared__ char smem[];
    ull*   xs  = (ull*)(smem + SM_XS);     // [k*128 + pair]
    float* xsf = (float*)(smem + SM_XS);   // scalar view: [(k*128+pair)*2 + lane]
    ull*   cs  = (ull*)(smem + SM_CS);     // [code*128 + k], (c,c) duplicated
    float* bs  = (float*)(smem + SM_BS);
    float* exd0 = (float*)(smem + SM_EXD0);
    float* exd1 = (float*)(smem + SM_EXD1);
    int*   exi0 = (int*)(smem + SM_EXI0);
    int*   exi1 = (int*)(smem + SM_EXI1);
    float* red  = (float*)(smem + SM_RED);

    const int t    = threadIdx.x;
    const int p    = t & 127;       // pair id
    const int h    = t >> 7;        // code-half (0: codes 0-7 of tile, 1: 8-15)
    const int base = blockIdx.x * ROWS_CTA;

    // ---- stage x rows pair-packed: lane0 = row base+r, lane1 = row base+128+r
    {
        const float4* x4 = (const float4*)(x + (size_t)base * DIM);
        #pragma unroll
        for (int i = 0; i < (ROWS_CTA * DIM / 4) / THREADS; i++) {   // 32 iters
            int idx  = t + THREADS * i;          // float4 index within CTA slab
            int row  = idx >> 5;                 // 32 float4 per row
            int posq = idx & 31;
            float4 v = x4[idx];
            int pr   = row & 127;
            int ln   = row >> 7;
            int k0   = posq * 4;
            xsf[((k0 + 0) * 128 + pr) * 2 + ln] = v.x;
            xsf[((k0 + 1) * 128 + pr) * 2 + ln] = v.y;
            xsf[((k0 + 2) * 128 + pr) * 2 + ln] = v.z;
            xsf[((k0 + 3) * 128 + pr) * 2 + ln] = v.w;
        }
    }
    __syncthreads();

    // ---- A per lane: fl( sum fl(x^2) ) via exact double accumulation.
    // (exactness + grid-translation-invariance => argmin matches any
    //  reference association up to ~2^-13-probability parity ties)
    float A0, A1;
    {
        double a0 = 0.0, a1 = 0.0;
        #pragma unroll 8
        for (int k = 0; k < DIM; k++) {
            float f0, f1;
            unpack2(xs[k * 128 + p], f0, f1);
            a0 += (double)__fmul_rn(f0, f0);
            a1 += (double)__fmul_rn(f1, f1);
        }
        A0 = (float)a0; A1 = (float)a1;
    }

    float best0 = INFINITY, best1 = INFINITY;
    int   bi0 = 0, bi1 = 0;

    for (int kt = 0; kt < KCODES / KC; kt++) {
        __syncthreads();
        // stage KC codes, duplicated (c,c) for lane-shared fma2
        {
            const float4* c4 = (const float4*)(cb + (size_t)kt * KC * DIM);
            #pragma unroll
            for (int i = 0; i < (KC * DIM / 4) / THREADS; i++) {     // 2 iters
                int idx  = t + THREADS * i;
                int code = idx >> 5;
                int posq = idx & 31;
                float4 v = c4[idx];
                ull* crow = cs + code * 128 + posq * 4;
                crow[0] = pack2(v.x, v.x);
                crow[1] = pack2(v.y, v.y);
                crow[2] = pack2(v.z, v.z);
                crow[3] = pack2(v.w, v.w);
            }
            if (t < KC) bs[t] = g_bsq[kt * KC + t];
        }
        __syncthreads();

        // 8 sequential fp32 fma chains (ascending k), two rows via lanes.
        ull acc[CJ];
        #pragma unroll
        for (int c = 0; c < CJ; c++) acc[c] = 0ull;
        const ull* cbase = cs + (h * CJ) * 128;
        #pragma unroll 4
        for (int k = 0; k < DIM; k++) {
            ull xv = xs[k * 128 + p];
            #pragma unroll
            for (int c = 0; c < CJ; c++)
                acc[c] = fma2(xv, cbase[c * 128 + k], acc[c]);
        }

        // d = fl( fl(A + B) - 2*dot )  — the reference's exact fp32 formula
        #pragma unroll
        for (int c = 0; c < CJ; c++) {
            float dot0, dot1;
            unpack2(acc[c], dot0, dot1);
            float B    = bs[h * CJ + c];
            int   gidx = kt * KC + h * CJ + c;
            float d0 = __fadd_rn(__fadd_rn(A0, B), -(2.0f * dot0));
            float d1 = __fadd_rn(__fadd_rn(A1, B), -(2.0f * dot1));
            if (d0 < best0) { best0 = d0; bi0 = gidx; }
            if (d1 < best1) { best1 = d1; bi1 = gidx; }
        }
    }

    // ---- combine halves: lexicographic (d, idx) => global lowest-index argmin
    __syncthreads();
    if (h == 1) {
        exd0[p] = best0; exi0[p] = bi0;
        exd1[p] = best1; exi1[p] = bi1;
    }
    __syncthreads();
    if (h == 0) {
        float od = exd0[p]; int oi = exi0[p];
        if (od < best0 || (od == best0 && oi < bi0)) { best0 = od; bi0 = oi; }
        od = exd1[p]; oi = exi1[p];
        if (od < best1 || (od == best1 && oi < bi1)) { best1 = od; bi1 = oi; }
        exi0[p] = bi0; exi1[p] = bi1;   // publish winners
    }
    __syncthreads();

    // ---- epilogue: each thread handles one row (h picks lane)
    const int myrow  = base + h * 128 + p;
    const int mycode = (h == 0) ? exi0[p] : exi1[p];
    g_idx[myrow] = mycode;
    atomicAdd(&g_counts[mycode], 1);

    float lsum = 0.f;
    {
        const float4* q4 = (const float4*)(cb + (size_t)mycode * DIM);
        float* qo = outq + (size_t)myrow * DIM;   // base 4B-aligned only
        #pragma unroll 4
        for (int i = 0; i < DIM / 4; i++) {
            float4 q = q4[i];
            float xa = xsf[((4 * i + 0) * 128 + p) * 2 + h];
            float xb = xsf[((4 * i + 1) * 128 + p) * 2 + h];
            float xc = xsf[((4 * i + 2) * 128 + p) * 2 + h];
            float xd = xsf[((4 * i + 3) * 128 + p) * 2 + h];
            float d0 = q.x - xa, d1 = q.y - xb, d2 = q.z - xc, d3 = q.w - xd;
            lsum += d0 * d0 + d1 * d1 + d2 * d2 + d3 * d3;
            qo[4 * i + 0] = q.x; qo[4 * i + 1] = q.y;
            qo[4 * i + 2] = q.z; qo[4 * i + 3] = q.w;
        }
    }

    __syncthreads();
    red[t] = lsum;
    __syncthreads();
    for (int s = 128; s > 0; s >>= 1) {
        if (t < s) red[t] += red[t + s];
        __syncthreads();
    }
    if (t == 0) g_bloss[blockIdx.x] = red[0];
}

// ============================================================
// 3) Encodings: fused zero + one-hot scatter
// ============================================================
__global__ void enc_kernel(float* __restrict__ oute) {
    const int n   = blockIdx.x;
    const int idx = g_idx[n];
    float2* row = (float2*)(oute + (size_t)n * KCODES);
    const int t = threadIdx.x;
    #pragma unroll
    for (int i = 0; i < (KCODES / 2) / 128; i++) {
        int p2 = t + 128 * i;
        int p  = p2 * 2;
        float2 v;
        v.x = (p     == idx) ? 1.f : 0.f;
        v.y = (p + 1 == idx) ? 1.f : 0.f;
        row[p2] = v;
    }
}

// ============================================================
// 4) Finalize: loss + perplexity scalars
// ============================================================
__global__ void fin_kernel(float* __restrict__ out_loss,
                           float* __restrict__ out_perp) {
    __shared__ float sh[1024];
    const int t = threadIdx.x;

    float c = (float)g_counts[t];
    float p = c * (1.0f / (float)N_PTS);
    sh[t] = p * logf(p + 1e-10f);
    __syncthreads();
    for (int s = 512; s > 0; s >>= 1) {
        if (t < s) sh[t] += sh[t + s];
        __syncthreads();
    }
    float ent = sh[0];
    __syncthreads();

    sh[t] = (t < 512) ? g_bloss[t] : 0.f;
    __syncthreads();
    for (int s = 512; s > 0; s >>= 1) {
        if (t < s) sh[t] += sh[t + s];
        __syncthreads();
    }
    if (t == 0) {
        *out_perp = expf(-ent);
        *out_loss = 1.25f * sh[0] / (float)((size_t)N_PTS * DIM);
    }
}

// ============================================================
// launch
// ============================================================
extern "C" void kernel_launch(void* const* d_in, const int* in_sizes, int n_in,
                              void* d_out, int out_size) {
    const float* x  = (const float*)d_in[0];   // [65536, 128] f32
    const float* cb = (const float*)d_in[1];   // [1024, 128]  f32
    float* out  = (float*)d_out;
    float* outq = out + 1;
    float* outp = out + 1 + (size_t)N_PTS * DIM;
    float* oute = outp + 1;

    static int attr_done = 0;
    if (!attr_done) {
        cudaFuncSetAttribute(vq_main, cudaFuncAttributeMaxDynamicSharedMemorySize,
                             SM_TOTAL);
        attr_done = 1;
    }

    prep_kernel<<<8, 128>>>(cb);
    vq_main<<<NCTAS, THREADS, SM_TOTAL>>>(x, cb, outq);
    enc_kernel<<<N_PTS, 128>>>(oute);
    fin_kernel<<<1, 1024>>>(out, outp);
}

// round 7
// speedup vs baseline: 1.3146x; 1.3146x over previous
#include <cuda_runtime.h>
#include <cstdint>
#include <math.h>

#define N_PTS    65536
#define DIM      128
#define KCODES   1024
#define KC       64          // codes per smem tile
#define NTILES   (KCODES / KC)   // 16
#define CJ       8           // codes per thread per tile
#define RP       4           // row-pairs per thread
#define ROWS_CTA 256
#define THREADS  256
#define NCTAS    (N_PTS / ROWS_CTA)   // 256

typedef unsigned long long ull;

// ---- f32x2 packed math (sm_103a); lanes are IEEE fp32 fma.rn ----
__device__ __forceinline__ ull pack2(float a, float b) {
    ull r; asm("mov.b64 %0, {%1, %2};" : "=l"(r) : "f"(a), "f"(b)); return r;
}
__device__ __forceinline__ ull dup2(float a) {
    ull r; asm("mov.b64 %0, {%1, %1};" : "=l"(r) : "f"(a)); return r;
}
__device__ __forceinline__ void unpack2(ull v, float& a, float& b) {
    asm("mov.b64 {%0, %1}, %2;" : "=f"(a), "=f"(b) : "l"(v));
}
__device__ __forceinline__ ull fma2(ull a, ull b, ull c) {
    ull d; asm("fma.rn.f32x2 %0, %1, %2, %3;" : "=l"(d) : "l"(a), "l"(b), "l"(c)); return d;
}

// ---- device scratch ----
__device__ float g_bsq[KCODES];
__device__ int   g_counts[KCODES];
__device__ float g_bloss[512];     // only [0..NCTAS) written; rest stay 0

// smem layout (bytes)
#define SM_XS    0                          // ull  xs[128 k][128 pair] = 131072
#define SM_CS    131072                     // f32  cs[KC][128 k]       = 32768
#define SM_BS    (SM_CS + 32768)            // f32  bs[KC]              = 256
#define SM_A     (SM_BS + 256)              // f32  sA[256]  (pair*2+lane)
#define SM_SD    (SM_A + 1024)              // f32  sd[8][256]          = 8192
#define SM_SI    (SM_SD + 8192)             // int  si[8][256]          = 8192
#define SM_SIDX  (SM_SI + 8192)             // int  sidx[256]           = 1024
#define SM_RED   (SM_SIDX + 1024)           // f32  red[256]            = 1024
#define SM_TOTAL (SM_RED + 1024)            // 183552 bytes

// ============================================================
// 1) B_k = fl( sum fl(c^2) ) via exact double accumulation
// ============================================================
__global__ void prep_kernel(const float* __restrict__ cb) {
    int k = blockIdx.x * blockDim.x + threadIdx.x;
    if (k < KCODES) {
        const float* c = cb + (size_t)k * DIM;
        double s = 0.0;
        #pragma unroll 8
        for (int i = 0; i < DIM; i++) {
            float q = __fmul_rn(c[i], c[i]);
            s += (double)q;
        }
        g_bsq[k] = (float)s;
        g_counts[k] = 0;
    }
}

// ============================================================
// 2) Main: register-tiled (RP pairs x CJ codes), bit-faithful
//    sequential fp32 chains, fused quantized + encodings + loss
// ============================================================
__global__ __launch_bounds__(THREADS, 1)
void vq_main(const float* __restrict__ x, const float* __restrict__ cb,
             float* __restrict__ outq, float* __restrict__ oute) {
    extern __shared__ char smem[];
    ull*    xs   = (ull*)(smem + SM_XS);     // [k*128 + pair], (row p, row p+128)
    float*  xsf  = (float*)(smem + SM_XS);   // scalar view
    float*  cs   = (float*)(smem + SM_CS);   // [code*128 + k] scalar
    float2* cs2  = (float2*)(smem + SM_CS);  // [code*64 + kk]
    float*  bs   = (float*)(smem + SM_BS);
    float*  sA   = (float*)(smem + SM_A);
    float*  sd   = (float*)(smem + SM_SD);
    int*    si   = (int*)(smem + SM_SI);
    int*    sidx = (int*)(smem + SM_SIDX);
    float*  red  = (float*)(smem + SM_RED);

    const int t    = threadIdx.x;
    const int pg   = t & 31;     // pair group: pairs 4pg..4pg+3
    const int cg   = t >> 5;     // code group: codes cg*8..cg*8+7 within tile
    const int base = blockIdx.x * ROWS_CTA;

    // ---- stage x pair-packed: lane0 = row base+p, lane1 = row base+128+p
    {
        const float4* x4 = (const float4*)(x + (size_t)base * DIM);
        #pragma unroll
        for (int i = 0; i < (ROWS_CTA * DIM / 4) / THREADS; i++) {   // 32
            int idx  = t + THREADS * i;
            int row  = idx >> 5;
            int posq = idx & 31;
            float4 v = x4[idx];
            int pr = row & 127, ln = row >> 7, k0 = posq * 4;
            xsf[((k0 + 0) * 128 + pr) * 2 + ln] = v.x;
            xsf[((k0 + 1) * 128 + pr) * 2 + ln] = v.y;
            xsf[((k0 + 2) * 128 + pr) * 2 + ln] = v.z;
            xsf[((k0 + 3) * 128 + pr) * 2 + ln] = v.w;
        }
    }
    __syncthreads();

    // ---- A = fl( exact double sum of fl(x^2) ), once per pair (threads t<32)
    if (t < 32) {
        #pragma unroll
        for (int r = 0; r < RP; r++) {
            int pr = 4 * t + r;
            double a0 = 0.0, a1 = 0.0;
            for (int k = 0; k < DIM; k++) {
                float f0, f1;
                unpack2(xs[k * 128 + pr], f0, f1);
                a0 += (double)__fmul_rn(f0, f0);
                a1 += (double)__fmul_rn(f1, f1);
            }
            sA[pr * 2 + 0] = (float)a0;
            sA[pr * 2 + 1] = (float)a1;
        }
    }
    __syncthreads();

    float A0[RP], A1[RP];
    #pragma unroll
    for (int r = 0; r < RP; r++) {
        A0[r] = sA[(4 * pg + r) * 2 + 0];
        A1[r] = sA[(4 * pg + r) * 2 + 1];
    }

    float best0[RP], best1[RP];
    int   bi0[RP],   bi1[RP];
    #pragma unroll
    for (int r = 0; r < RP; r++) {
        best0[r] = INFINITY; best1[r] = INFINITY; bi0[r] = 0; bi1[r] = 0;
    }

    const ull* xp = xs + 4 * pg;

    for (int kt = 0; kt < NTILES; kt++) {
        __syncthreads();
        // stage KC codes scalar [code][k] (direct row-major copy)
        {
            const float4* c4 = (const float4*)(cb + (size_t)kt * KC * DIM);
            float4* s4 = (float4*)cs;
            #pragma unroll
            for (int i = 0; i < (KC * DIM / 4) / THREADS; i++)       // 8
                s4[t + THREADS * i] = c4[t + THREADS * i];
            if (t < KC) bs[t] = g_bsq[kt * KC + t];
        }
        __syncthreads();

        ull acc[RP][CJ];
        #pragma unroll
        for (int r = 0; r < RP; r++)
            #pragma unroll
            for (int c = 0; c < CJ; c++) acc[r][c] = 0ull;

        const float2* cb2 = cs2 + (cg * CJ) * 64;

        #pragma unroll 2
        for (int kk = 0; kk < DIM / 2; kk++) {
            ull xa[RP], xb[RP];
            const ull* xrow = xp + kk * 256;
            #pragma unroll
            for (int r = 0; r < RP; r++) { xa[r] = xrow[r]; xb[r] = xrow[128 + r]; }
            #pragma unroll
            for (int c = 0; c < CJ; c++) {
                float2 cv = cb2[c * 64 + kk];
                ull ca = dup2(cv.x);
                ull cbv = dup2(cv.y);
                #pragma unroll
                for (int r = 0; r < RP; r++)
                    acc[r][c] = fma2(xa[r], ca, acc[r][c]);   // k = 2kk
                #pragma unroll
                for (int r = 0; r < RP; r++)
                    acc[r][c] = fma2(xb[r], cbv, acc[r][c]);  // k = 2kk+1
            }
        }

        // d = fl( fl(A + B) - 2*dot ) — reference's exact fp32 formula
        #pragma unroll
        for (int c = 0; c < CJ; c++) {
            float B    = bs[cg * CJ + c];
            int   gidx = kt * KC + cg * CJ + c;
            #pragma unroll
            for (int r = 0; r < RP; r++) {
                float d0f, d1f;
                unpack2(acc[r][c], d0f, d1f);
                float d0 = __fadd_rn(__fadd_rn(A0[r], B), -(2.0f * d0f));
                float d1 = __fadd_rn(__fadd_rn(A1[r], B), -(2.0f * d1f));
                if (d0 < best0[r]) { best0[r] = d0; bi0[r] = gidx; }
                if (d1 < best1[r]) { best1[r] = d1; bi1[r] = gidx; }
            }
        }
    }

    // ---- cross-code-group lexicographic (d, idx) reduction
    __syncthreads();
    #pragma unroll
    for (int r = 0; r < RP; r++) {
        int pr = 4 * pg + r;
        sd[cg * 256 + pr * 2 + 0] = best0[r];  si[cg * 256 + pr * 2 + 0] = bi0[r];
        sd[cg * 256 + pr * 2 + 1] = best1[r];  si[cg * 256 + pr * 2 + 1] = bi1[r];
    }
    __syncthreads();

    float bd = sd[t];  int bi = si[t];
    #pragma unroll
    for (int g = 1; g < 8; g++) {
        float od = sd[g * 256 + t]; int oi = si[g * 256 + t];
        if (od < bd || (od == bd && oi < bi)) { bd = od; bi = oi; }
    }
    const int mypair = t >> 1, mylane = t & 1;
    const int ro     = mylane * 128 + mypair;       // row within CTA
    sidx[ro] = bi;
    atomicAdd(&g_counts[bi], 1);

    // ---- quantized row + loss partial (per-thread row)
    float lsum = 0.f;
    {
        const float4* q4 = (const float4*)(cb + (size_t)bi * DIM);
        float* qo = outq + (size_t)(base + ro) * DIM;   // 4B-aligned only
        #pragma unroll 4
        for (int i = 0; i < DIM / 4; i++) {
            float4 q = q4[i];
            float xa = xsf[((4 * i + 0) * 128 + mypair) * 2 + mylane];
            float xb = xsf[((4 * i + 1) * 128 + mypair) * 2 + mylane];
            float xc = xsf[((4 * i + 2) * 128 + mypair) * 2 + mylane];
            float xd = xsf[((4 * i + 3) * 128 + mypair) * 2 + mylane];
            float d0 = q.x - xa, d1 = q.y - xb, d2 = q.z - xc, d3 = q.w - xd;
            lsum += d0 * d0 + d1 * d1 + d2 * d2 + d3 * d3;
            qo[4 * i + 0] = q.x; qo[4 * i + 1] = q.y;
            qo[4 * i + 2] = q.z; qo[4 * i + 3] = q.w;
        }
    }

    __syncthreads();
    red[t] = lsum;
    __syncthreads();
    for (int s = 128; s > 0; s >>= 1) {
        if (t < s) red[t] += red[t + s];
        __syncthreads();
    }
    if (t == 0) g_bloss[blockIdx.x] = red[0];

    // ---- fused encodings: cooperative coalesced one-hot rows
    // (sidx visible: written before the reduction syncs above)
    for (int r2 = 0; r2 < ROWS_CTA; r2++) {
        int idx = sidx[r2];
        float2* erow = (float2*)(oute + (size_t)(base + r2) * KCODES);
        int p2a = t,        pa = 2 * p2a;
        int p2b = t + 256,  pb = 2 * p2b;
        float2 va, vb;
        va.x = (pa     == idx) ? 1.f : 0.f;
        va.y = (pa + 1 == idx) ? 1.f : 0.f;
        vb.x = (pb     == idx) ? 1.f : 0.f;
        vb.y = (pb + 1 == idx) ? 1.f : 0.f;
        erow[p2a] = va;
        erow[p2b] = vb;
    }
}

// ============================================================
// 3) Finalize: loss + perplexity scalars
// ============================================================
__global__ void fin_kernel(float* __restrict__ out_loss,
                           float* __restrict__ out_perp) {
    __shared__ float sh[1024];
    const int t = threadIdx.x;

    float c = (float)g_counts[t];
    float p = c * (1.0f / (float)N_PTS);
    sh[t] = p * logf(p + 1e-10f);
    __syncthreads();
    for (int s = 512; s > 0; s >>= 1) {
        if (t < s) sh[t] += sh[t + s];
        __syncthreads();
    }
    float ent = sh[0];
    __syncthreads();

    sh[t] = (t < NCTAS) ? g_bloss[t] : 0.f;
    __syncthreads();
    for (int s = 512; s > 0; s >>= 1) {
        if (t < s) sh[t] += sh[t + s];
        __syncthreads();
    }
    if (t == 0) {
        *out_perp = expf(-ent);
        *out_loss = 1.25f * sh[0] / (float)((size_t)N_PTS * DIM);
    }
}

// ============================================================
// launch
// ============================================================
extern "C" void kernel_launch(void* const* d_in, const int* in_sizes, int n_in,
                              void* d_out, int out_size) {
    const float* x  = (const float*)d_in[0];   // [65536, 128] f32
    const float* cb = (const float*)d_in[1];   // [1024, 128]  f32
    float* out  = (float*)d_out;
    float* outq = out + 1;
    float* outp = out + 1 + (size_t)N_PTS * DIM;
    float* oute = outp + 1;

    static int attr_done = 0;
    if (!attr_done) {
        cudaFuncSetAttribute(vq_main, cudaFuncAttributeMaxDynamicSharedMemorySize,
                             SM_TOTAL);
        attr_done = 1;
    }

    prep_kernel<<<8, 128>>>(cb);
    vq_main<<<NCTAS, THREADS, SM_TOTAL>>>(x, cb, outq, oute);
    fin_kernel<<<1, 1024>>>(out, outp);
}